// round 8
// baseline (speedup 1.0000x reference)
#include <cuda_runtime.h>
#include <cuda_fp16.h>
#include <math.h>

#define NN 100000
#define NE 3200000
#define FIN 32
#define HD 64
#define NL 4
#define NA 6158
#define NG 64
#define WPAD 68

// ---------------- scratch (device globals; no allocation allowed) -------------
__device__ int   d_flag;
__device__ int   d_src[NE];
__device__ int   d_dst[NE];
__device__ int   d_batch32[NN];
__device__ int   d_deg[NN];
__device__ int   d_rowptr[NN + 1];
__device__ int   d_cursor[NN];
__device__ int   d_csr[NE];
__device__ float d_invdeg[NN];
__device__ float d_h0[NN * HD];
__device__ float d_h1[NN * HD];
__device__ __half2 d_hh[NN * 32];
__device__ float d_agg[NN * HD];
__device__ float d_gsum[NG * HD];
__device__ int   d_gcnt[NG];
__device__ int   d_part[256];

// ---------------- f32x2 packed-FMA helpers -------------------------------------
__device__ __forceinline__ unsigned long long pack2(float x) {
    unsigned long long r;
    asm("mov.b64 %0, {%1, %1};" : "=l"(r) : "f"(x));
    return r;
}
__device__ __forceinline__ void ffma2(unsigned long long& d,
                                      unsigned long long a,
                                      unsigned long long b) {
    asm("fma.rn.f32x2 %0, %1, %2, %0;" : "+l"(d) : "l"(a), "l"(b));
}
__device__ __forceinline__ void unpack2(unsigned long long v, float& lo, float& hi) {
    asm("mov.b64 {%0, %1}, %2;" : "=f"(lo), "=f"(hi) : "l"(v));
}

// ---------------- encoder: h0 = relu(x @ W_enc^T + b_enc) + zero accumulators --
__global__ void k_encoder(const float* __restrict__ x,
                          const float* __restrict__ Wenc,
                          const float* __restrict__ benc) {
    __shared__ float Ws[FIN * HD];
    __shared__ float bs[HD];
    int t = threadIdx.x;
    int gid = blockIdx.x * blockDim.x + t;
    if (gid < NN) d_deg[gid] = 0;
    if (gid < NG) d_gcnt[gid] = 0;
    if (gid < NG * HD) d_gsum[gid] = 0.f;

    for (int i = t; i < HD * FIN; i += blockDim.x) {
        int j = i / FIN, k = i % FIN;
        Ws[k * HD + j] = Wenc[i];
    }
    if (t < HD) bs[t] = benc[t];
    __syncthreads();
    if (gid >= NN * 32) return;
    int n = gid >> 5, j2 = gid & 31;
    int j = 2 * j2;
    const float* xr = x + n * FIN;
    float a0 = bs[j], a1 = bs[j + 1];
#pragma unroll
    for (int k = 0; k < FIN; k += 4) {
        float4 xv = *(const float4*)(xr + k);
        float2 w0 = *(const float2*)(&Ws[k * HD + j]);
        float2 w1 = *(const float2*)(&Ws[(k + 1) * HD + j]);
        float2 w2 = *(const float2*)(&Ws[(k + 2) * HD + j]);
        float2 w3 = *(const float2*)(&Ws[(k + 3) * HD + j]);
        a0 += xv.x * w0.x + xv.y * w1.x + xv.z * w2.x + xv.w * w3.x;
        a1 += xv.x * w0.y + xv.y * w1.y + xv.z * w2.y + xv.w * w3.y;
    }
    a0 = fmaxf(a0, 0.f);
    a1 = fmaxf(a1, 0.f);
    ((float2*)d_h0)[gid] = make_float2(a0, a1);
    d_hh[gid] = __floats2half2_rn(a0, a1);
}

// ---------------- detect dtype (flag only) --------------------------------------
__global__ void k_detect(const void* edge) {
    if (threadIdx.x != 0) return;
    const unsigned int* w = (const unsigned int*)edge;
    int zeros = 0;
    for (int j = 0; j < 128; j++) if (w[2 * j + 1] == 0u) zeros++;
    d_flag = (zeros >= 120) ? 1 : 0;
}

// converts edges AND accumulates in-degree for dst (fused)
__global__ void k_convert_edges(const void* edge) {
    int i = blockIdx.x * blockDim.x + threadIdx.x;
    if (i >= 2 * NE) return;
    int v;
    if (d_flag) v = (int)((const long long*)edge)[i];
    else        v = ((const int*)edge)[i];
    if (i < NE) d_src[i] = v;
    else        { d_dst[i - NE] = v; atomicAdd(&d_deg[v], 1); }
}

// ---------------- CSR build (scan over degrees) --------------------------------
__global__ void k_scan_a() {
    __shared__ int ts[256];
    int b = blockIdx.x, t = threadIdx.x;
    int base = b * 1024 + t * 4;
    int v[4];
    int s = 0;
#pragma unroll
    for (int j = 0; j < 4; j++) {
        int idx = base + j;
        v[j] = (idx < NN) ? d_deg[idx] : 0;
        s += v[j];
    }
    ts[t] = s;
    __syncthreads();
    for (int off = 1; off < 256; off <<= 1) {
        int x = (t >= off) ? ts[t - off] : 0;
        __syncthreads();
        ts[t] += x;
        __syncthreads();
    }
    int run = ts[t] - s;
#pragma unroll
    for (int j = 0; j < 4; j++) {
        int idx = base + j;
        if (idx < NN) d_rowptr[idx] = run;
        run += v[j];
    }
    if (t == 255) d_part[b] = ts[255];
}

// scan finalize (partial-scan fused, block-redundant) + invdeg + batch + counts
__global__ void k_scan_c(const void* batch) {
    __shared__ int ps[128];
    int t = threadIdx.x;
    int orig = (t < 98) ? d_part[t] : 0;
    if (t < 128) ps[t] = orig;
    __syncthreads();
    for (int off = 1; off < 128; off <<= 1) {
        int x = (t >= off && t < 128) ? ps[t - off] : 0;
        __syncthreads();
        if (t < 128) ps[t] += x;
        __syncthreads();
    }
    if (t < 128) ps[t] -= orig;   // exclusive
    __syncthreads();

    int i = blockIdx.x * blockDim.x + t;
    if (i == 0) d_rowptr[NN] = NE;
    if (i >= NN) return;
    int r = d_rowptr[i] + ps[i >> 10];
    d_rowptr[i] = r;
    d_cursor[i] = r;
    d_invdeg[i] = 1.0f / fmaxf((float)d_deg[i], 1.0f);
    int b;
    if (d_flag) b = (int)((const long long*)batch)[i];
    else        b = ((const int*)batch)[i];
    d_batch32[i] = b;
    atomicAdd(&d_gcnt[b], 1);
}

__global__ void k_scatter() {
    int e = blockIdx.x * blockDim.x + threadIdx.x;
    if (e >= NE) return;
    int dd = d_dst[e];
    int pos = atomicAdd(&d_cursor[dd], 1);
    d_csr[pos] = d_src[e];
}

// ---------------- aggregation: agg[n] = mean_{e: dst=n} h_fp16[src[e]] ---------
// R4-proven shape: warp per node, fp16x2 per lane, MLP 8, dual accumulators.
__global__ void k_aggregate() {
    int w = (blockIdx.x * blockDim.x + threadIdx.x) >> 5;
    if (w >= NN) return;
    int lane = threadIdx.x & 31;
    int beg = d_rowptr[w], end = d_rowptr[w + 1];
    const __half2* __restrict__ hp = d_hh;
    float ax0 = 0.f, ay0 = 0.f, ax1 = 0.f, ay1 = 0.f;
    int i = beg;
    for (; i + 8 <= end; i += 8) {
        int s0 = d_csr[i + 0], s1 = d_csr[i + 1], s2 = d_csr[i + 2], s3 = d_csr[i + 3];
        int s4 = d_csr[i + 4], s5 = d_csr[i + 5], s6 = d_csr[i + 6], s7 = d_csr[i + 7];
        float2 v0 = __half22float2(hp[s0 * 32 + lane]);
        float2 v1 = __half22float2(hp[s1 * 32 + lane]);
        float2 v2 = __half22float2(hp[s2 * 32 + lane]);
        float2 v3 = __half22float2(hp[s3 * 32 + lane]);
        float2 v4 = __half22float2(hp[s4 * 32 + lane]);
        float2 v5 = __half22float2(hp[s5 * 32 + lane]);
        float2 v6 = __half22float2(hp[s6 * 32 + lane]);
        float2 v7 = __half22float2(hp[s7 * 32 + lane]);
        ax0 += v0.x + v1.x + v2.x + v3.x;
        ay0 += v0.y + v1.y + v2.y + v3.y;
        ax1 += v4.x + v5.x + v6.x + v7.x;
        ay1 += v4.y + v5.y + v6.y + v7.y;
    }
    for (; i < end; i++) {
        float2 v = __half22float2(hp[d_csr[i] * 32 + lane]);
        ax0 += v.x; ay0 += v.y;
    }
    float id = d_invdeg[w];
    ((float2*)d_agg)[w * 32 + lane] = make_float2((ax0 + ax1) * id, (ay0 + ay1) * id);
}

// ---------------- layer: h_out = relu(agg@Wl^T + bl + h@Wr^T) + h --------------
__global__ void __launch_bounds__(256, 2)
k_layer(int sel,
        const float* __restrict__ Wl, const float* __restrict__ bl,
        const float* __restrict__ Wr) {
    const float* h    = sel ? d_h1 : d_h0;
    float*       hout = sel ? d_h0 : d_h1;
    __shared__ float S[2 * HD * WPAD + HD];
    float* Wls = S;
    float* Wrs = S + HD * WPAD;
    float* bls = S + 2 * HD * WPAD;
    int t = threadIdx.x;
    for (int i = t; i < HD * HD; i += 256) {
        int j = i >> 6, k = i & 63;
        Wls[k * WPAD + j] = Wl[i];
        Wrs[k * WPAD + j] = Wr[i];
    }
    if (t < HD) bls[t] = bl[t];
    __syncthreads();

    int p    = t & 127;
    int jh   = t >> 7;
    int base = blockIdx.x * 256;
    int n0 = base + 2 * p, n1 = n0 + 1;
    bool v0 = (n0 < NN), v1 = (n1 < NN);

    unsigned long long accA[16], accB[16];
    {
        const unsigned long long* bp2 = (const unsigned long long*)(bls + jh * 32);
#pragma unroll
        for (int q = 0; q < 16; q++) { accA[q] = bp2[q]; accB[q] = bp2[q]; }
    }

    float oA[32], oB[32];
    if (v0) {
        const float4* __restrict__ arA = (const float4*)(d_agg + n0 * HD);
        const float4* __restrict__ hrA = (const float4*)(h + n0 * HD);
        const float4* __restrict__ arB = (const float4*)(d_agg + n1 * HD);
        const float4* __restrict__ hrB = (const float4*)(h + n1 * HD);
#pragma unroll 2
        for (int k4 = 0; k4 < 16; k4++) {
            float4 aA = arA[k4], hA = hrA[k4];
            float4 aB, hB;
            if (v1) { aB = arB[k4]; hB = hrB[k4]; }
            else    { aB = make_float4(0, 0, 0, 0); hB = aB; }
            float aAv[4] = {aA.x, aA.y, aA.z, aA.w};
            float hAv[4] = {hA.x, hA.y, hA.z, hA.w};
            float aBv[4] = {aB.x, aB.y, aB.z, aB.w};
            float hBv[4] = {hB.x, hB.y, hB.z, hB.w};
#pragma unroll
            for (int kk = 0; kk < 4; kk++) {
                int k = k4 * 4 + kk;
                const ulonglong2* __restrict__ wl =
                    (const ulonglong2*)(Wls + k * WPAD + jh * 32);
                const ulonglong2* __restrict__ wr =
                    (const ulonglong2*)(Wrs + k * WPAD + jh * 32);
                unsigned long long aAp = pack2(aAv[kk]);
                unsigned long long hAp = pack2(hAv[kk]);
                unsigned long long aBp = pack2(aBv[kk]);
                unsigned long long hBp = pack2(hBv[kk]);
#pragma unroll
                for (int j4 = 0; j4 < 8; j4++) {
                    ulonglong2 L = wl[j4];
                    ulonglong2 R = wr[j4];
                    ffma2(accA[2 * j4 + 0], aAp, L.x);
                    ffma2(accA[2 * j4 + 1], aAp, L.y);
                    ffma2(accA[2 * j4 + 0], hAp, R.x);
                    ffma2(accA[2 * j4 + 1], hAp, R.y);
                    ffma2(accB[2 * j4 + 0], aBp, L.x);
                    ffma2(accB[2 * j4 + 1], aBp, L.y);
                    ffma2(accB[2 * j4 + 0], hBp, R.x);
                    ffma2(accB[2 * j4 + 1], hBp, R.y);
                }
            }
        }
#pragma unroll
        for (int q = 0; q < 16; q++) {
            unpack2(accA[q], oA[2 * q], oA[2 * q + 1]);
            unpack2(accB[q], oB[2 * q], oB[2 * q + 1]);
        }
        const float4* __restrict__ resA = (const float4*)(h + n0 * HD + jh * 32);
#pragma unroll
        for (int f = 0; f < 8; f++) {
            float4 r = resA[f];
            oA[4 * f + 0] = fmaxf(oA[4 * f + 0], 0.f) + r.x;
            oA[4 * f + 1] = fmaxf(oA[4 * f + 1], 0.f) + r.y;
            oA[4 * f + 2] = fmaxf(oA[4 * f + 2], 0.f) + r.z;
            oA[4 * f + 3] = fmaxf(oA[4 * f + 3], 0.f) + r.w;
        }
        if (v1) {
            const float4* __restrict__ resB = (const float4*)(h + n1 * HD + jh * 32);
#pragma unroll
            for (int f = 0; f < 8; f++) {
                float4 r = resB[f];
                oB[4 * f + 0] = fmaxf(oB[4 * f + 0], 0.f) + r.x;
                oB[4 * f + 1] = fmaxf(oB[4 * f + 1], 0.f) + r.y;
                oB[4 * f + 2] = fmaxf(oB[4 * f + 2], 0.f) + r.z;
                oB[4 * f + 3] = fmaxf(oB[4 * f + 3], 0.f) + r.w;
            }
        }
    }

    // staged, coalesced output: 2 waves of 128 nodes each (stage reuses W smem)
    float* stage = S;
#pragma unroll
    for (int wv = 0; wv < 2; wv++) {
        __syncthreads();
        if ((p >> 6) == wv && v0) {
            int ln = 2 * (p & 63);
            float4* sA = (float4*)(stage + ln * WPAD + jh * 32);
#pragma unroll
            for (int f = 0; f < 8; f++)
                sA[f] = make_float4(oA[4 * f], oA[4 * f + 1], oA[4 * f + 2], oA[4 * f + 3]);
            if (v1) {
                float4* sB = (float4*)(stage + (ln + 1) * WPAD + jh * 32);
#pragma unroll
                for (int f = 0; f < 8; f++)
                    sB[f] = make_float4(oB[4 * f], oB[4 * f + 1], oB[4 * f + 2], oB[4 * f + 3]);
            }
        }
        __syncthreads();
        for (int i2 = t; i2 < 2048; i2 += 256) {
            int node = i2 >> 4, f = i2 & 15;
            int gn = base + wv * 128 + node;
            if (gn < NN) {
                float4 vv = *(const float4*)(stage + node * WPAD + f * 4);
                *(float4*)(hout + gn * 64 + f * 4) = vv;
                __half2 l2 = __floats2half2_rn(vv.x, vv.y);
                __half2 h2 = __floats2half2_rn(vv.z, vv.w);
                unsigned int ul = *(unsigned int*)&l2;
                unsigned int uh = *(unsigned int*)&h2;
                ((uint2*)d_hh)[gn * 16 + f] = make_uint2(ul, uh);
            }
        }
    }
}

// ---------------- global mean pool ---------------------------------------------
__global__ void k_pool(int sel) {
    const float* h = sel ? d_h1 : d_h0;
    int t = threadIdx.x;
    int n0 = blockIdx.x * 256;
    if (n0 >= NN) return;
    int nend = n0 + 256; if (nend > NN) nend = NN;
    int cur = d_batch32[n0];
    float acc = 0.f;
    for (int n = n0; n < nend; n++) {
        int g = d_batch32[n];
        if (g != cur) {
            atomicAdd(&d_gsum[cur * HD + t], acc);
            acc = 0.f;
            cur = g;
        }
        acc += h[n * HD + t];
    }
    atomicAdd(&d_gsum[cur * HD + t], acc);
}

// ---------------- heads: policy (blocks 0..48) + value (last block) -------------
__global__ void __launch_bounds__(128)
k_policy(const float* __restrict__ Wp, const float* __restrict__ bp,
         const float* __restrict__ Wv, const float* __restrict__ bv,
         float* __restrict__ out) {
    __shared__ float repr[NG * HD];
    int t = threadIdx.x;
    for (int i = t; i < NG * HD; i += 128) {
        int g = i >> 6;
        repr[i] = d_gsum[i] / fmaxf((float)d_gcnt[g], 1.f);
    }
    __syncthreads();

    if (blockIdx.x == gridDim.x - 1) {   // value head
        int g = t;
        if (g >= NG) return;
        float acc = 0.f;
#pragma unroll
        for (int k = 0; k < HD; k++) acc += repr[g * HD + k] * Wv[k];
        out[NG * NA + g] = tanhf(acc + bv[0]);
        return;
    }

    int a = blockIdx.x * 128 + t;
    if (a >= NA) return;
    float acc[NG];
#pragma unroll
    for (int g = 0; g < NG; g++) acc[g] = 0.f;
    const float4* __restrict__ wr = (const float4*)(Wp + a * HD);
#pragma unroll 2
    for (int k4 = 0; k4 < 16; k4++) {
        float4 w = wr[k4];
#pragma unroll
        for (int g = 0; g < NG; g++) {
            float4 r = *(const float4*)(&repr[g * HD + k4 * 4]);
            acc[g] += w.x * r.x + w.y * r.y + w.z * r.z + w.w * r.w;
        }
    }
    float bias = bp[a];
#pragma unroll
    for (int g = 0; g < NG; g++) out[g * NA + a] = acc[g] + bias;
}

// ---------------- launcher -----------------------------------------------------
extern "C" void kernel_launch(void* const* d_in, const int* in_sizes, int n_in,
                              void* d_out, int out_size) {
    const float* x     = (const float*)d_in[0];
    const void*  edge  = d_in[1];
    const void*  batch = d_in[2];
    const float* Wenc  = (const float*)d_in[3];
    const float* benc  = (const float*)d_in[4];
    const float* Wl    = (const float*)d_in[5];
    const float* bl    = (const float*)d_in[6];
    const float* Wr    = (const float*)d_in[7];
    const float* Wp    = (const float*)d_in[8];
    const float* bp    = (const float*)d_in[9];
    const float* Wv    = (const float*)d_in[10];
    const float* bv    = (const float*)d_in[11];
    float* out = (float*)d_out;

    k_encoder<<<(NN * 32 + 255) / 256, 256>>>(x, Wenc, benc);  // idx 0
    k_detect<<<1, 32>>>(edge);                                 // idx 1
    k_convert_edges<<<(2 * NE + 255) / 256, 256>>>(edge);      // idx 2

    // INSTRUMENTATION: dummy aggregate at profiled stream index 3.
    // Reads previous replay's CSR (device globals persist; CSR is identical
    // every launch for fixed inputs). Output d_agg is overwritten by the real
    // aggregate below, so correctness is unaffected and fully deterministic.
    k_aggregate<<<(NN * 32 + 255) / 256, 256>>>();             // idx 3 (profiled)

    k_scan_a<<<98, 256>>>();                                   // idx 4
    k_scan_c<<<(NN + 255) / 256, 256>>>(batch);                // idx 5
    k_scatter<<<(NE + 255) / 256, 256>>>();                    // idx 6

    int sel = 0;
    for (int i = 0; i < NL; i++) {
        k_aggregate<<<(NN * 32 + 255) / 256, 256>>>();
        k_layer<<<(NN + 255) / 256, 256>>>(sel, Wl + i * HD * HD, bl + i * HD,
                                           Wr + i * HD * HD);
        sel ^= 1;
    }

    k_pool<<<(NN + 255) / 256, 64>>>(sel);
    k_policy<<<(NA + 127) / 128 + 1, 128>>>(Wp, bp, Wv, bv, out);
}

// round 9
// speedup vs baseline: 1.0362x; 1.0362x over previous
#include <cuda_runtime.h>
#include <cuda_fp16.h>
#include <math.h>

#define NN 100000
#define NE 3200000
#define FIN 32
#define HD 64
#define NL 4
#define NA 6158
#define NG 64
#define WPAD 68

// ---------------- scratch (device globals; no allocation allowed) -------------
__device__ int   d_flag;
__device__ int   d_src[NE];
__device__ int   d_dst[NE];
__device__ int   d_batch32[NN];
__device__ int   d_deg[NN];
__device__ int   d_rowptr[NN + 1];
__device__ int   d_cursor[NN];
__device__ int   d_csr[NE];
__device__ float d_invdeg[NN];
__device__ float d_h0[NN * HD];
__device__ float d_h1[NN * HD];
__device__ float d_scr[NN * HD];      // dummy-layer output (never read)
__device__ __half2 d_hh[NN * 32];
__device__ float d_agg[NN * HD];
__device__ float d_gsum[NG * HD];
__device__ int   d_gcnt[NG];
__device__ int   d_part[256];

// ---------------- f32x2 packed-FMA helpers -------------------------------------
__device__ __forceinline__ unsigned long long pack2(float x) {
    unsigned long long r;
    asm("mov.b64 %0, {%1, %1};" : "=l"(r) : "f"(x));
    return r;
}
__device__ __forceinline__ void ffma2(unsigned long long& d,
                                      unsigned long long a,
                                      unsigned long long b) {
    asm("fma.rn.f32x2 %0, %1, %2, %0;" : "+l"(d) : "l"(a), "l"(b));
}
__device__ __forceinline__ void unpack2(unsigned long long v, float& lo, float& hi) {
    asm("mov.b64 {%0, %1}, %2;" : "=f"(lo), "=f"(hi) : "l"(v));
}

// ---------------- encoder: h0 = relu(x @ W_enc^T + b_enc) + zero accumulators --
__global__ void k_encoder(const float* __restrict__ x,
                          const float* __restrict__ Wenc,
                          const float* __restrict__ benc) {
    __shared__ float Ws[FIN * HD];
    __shared__ float bs[HD];
    int t = threadIdx.x;
    int gid = blockIdx.x * blockDim.x + t;
    if (gid < NN) d_deg[gid] = 0;
    if (gid < NG) d_gcnt[gid] = 0;
    if (gid < NG * HD) d_gsum[gid] = 0.f;

    for (int i = t; i < HD * FIN; i += blockDim.x) {
        int j = i / FIN, k = i % FIN;
        Ws[k * HD + j] = Wenc[i];
    }
    if (t < HD) bs[t] = benc[t];
    __syncthreads();
    if (gid >= NN * 32) return;
    int n = gid >> 5, j2 = gid & 31;
    int j = 2 * j2;
    const float* xr = x + n * FIN;
    float a0 = bs[j], a1 = bs[j + 1];
#pragma unroll
    for (int k = 0; k < FIN; k += 4) {
        float4 xv = *(const float4*)(xr + k);
        float2 w0 = *(const float2*)(&Ws[k * HD + j]);
        float2 w1 = *(const float2*)(&Ws[(k + 1) * HD + j]);
        float2 w2 = *(const float2*)(&Ws[(k + 2) * HD + j]);
        float2 w3 = *(const float2*)(&Ws[(k + 3) * HD + j]);
        a0 += xv.x * w0.x + xv.y * w1.x + xv.z * w2.x + xv.w * w3.x;
        a1 += xv.x * w0.y + xv.y * w1.y + xv.z * w2.y + xv.w * w3.y;
    }
    a0 = fmaxf(a0, 0.f);
    a1 = fmaxf(a1, 0.f);
    ((float2*)d_h0)[gid] = make_float2(a0, a1);
    d_hh[gid] = __floats2half2_rn(a0, a1);
}

// convert edges + degree count; dtype detection done block-locally (warp ballot)
__global__ void k_convert_edges(const void* edge) {
    __shared__ int sflag;
    if (threadIdx.x < 32) {
        const unsigned int* w = (const unsigned int*)edge;
        unsigned int m0 = __ballot_sync(0xffffffffu, w[2 * threadIdx.x + 1] == 0u);
        unsigned int m1 = __ballot_sync(0xffffffffu, w[2 * (threadIdx.x + 32) + 1] == 0u);
        if (threadIdx.x == 0) {
            int f = (__popc(m0) + __popc(m1) >= 60) ? 1 : 0;
            sflag = f;
            if (blockIdx.x == 0) d_flag = f;   // for k_scan_c (batch conversion)
        }
    }
    __syncthreads();
    int i = blockIdx.x * blockDim.x + threadIdx.x;
    if (i >= 2 * NE) return;
    int v;
    if (sflag) v = (int)((const long long*)edge)[i];
    else       v = ((const int*)edge)[i];
    if (i < NE) d_src[i] = v;
    else        { d_dst[i - NE] = v; atomicAdd(&d_deg[v], 1); }
}

// ---------------- CSR build (scan over degrees) --------------------------------
__global__ void k_scan_a() {
    __shared__ int ts[256];
    int b = blockIdx.x, t = threadIdx.x;
    int base = b * 1024 + t * 4;
    int v[4];
    int s = 0;
#pragma unroll
    for (int j = 0; j < 4; j++) {
        int idx = base + j;
        v[j] = (idx < NN) ? d_deg[idx] : 0;
        s += v[j];
    }
    ts[t] = s;
    __syncthreads();
    for (int off = 1; off < 256; off <<= 1) {
        int x = (t >= off) ? ts[t - off] : 0;
        __syncthreads();
        ts[t] += x;
        __syncthreads();
    }
    int run = ts[t] - s;
#pragma unroll
    for (int j = 0; j < 4; j++) {
        int idx = base + j;
        if (idx < NN) d_rowptr[idx] = run;
        run += v[j];
    }
    if (t == 255) d_part[b] = ts[255];
}

// scan finalize (partial-scan fused, block-redundant) + invdeg + batch + counts
__global__ void k_scan_c(const void* batch) {
    __shared__ int ps[128];
    int t = threadIdx.x;
    int orig = (t < 98) ? d_part[t] : 0;
    if (t < 128) ps[t] = orig;
    __syncthreads();
    for (int off = 1; off < 128; off <<= 1) {
        int x = (t >= off && t < 128) ? ps[t - off] : 0;
        __syncthreads();
        if (t < 128) ps[t] += x;
        __syncthreads();
    }
    if (t < 128) ps[t] -= orig;   // exclusive
    __syncthreads();

    int i = blockIdx.x * blockDim.x + t;
    if (i == 0) d_rowptr[NN] = NE;
    if (i >= NN) return;
    int r = d_rowptr[i] + ps[i >> 10];
    d_rowptr[i] = r;
    d_cursor[i] = r;
    d_invdeg[i] = 1.0f / fmaxf((float)d_deg[i], 1.0f);
    int b;
    if (d_flag) b = (int)((const long long*)batch)[i];
    else        b = ((const int*)batch)[i];
    d_batch32[i] = b;
    atomicAdd(&d_gcnt[b], 1);
}

__global__ void k_scatter() {
    int e = blockIdx.x * blockDim.x + threadIdx.x;
    if (e >= NE) return;
    int dd = d_dst[e];
    int pos = atomicAdd(&d_cursor[dd], 1);
    d_csr[pos] = d_src[e];
}

// ---------------- aggregation: agg[n] = mean_{e: dst=n} h_fp16[src[e]] ---------
__global__ void k_aggregate() {
    int w = (blockIdx.x * blockDim.x + threadIdx.x) >> 5;
    if (w >= NN) return;
    int lane = threadIdx.x & 31;
    int beg = d_rowptr[w], end = d_rowptr[w + 1];
    const __half2* __restrict__ hp = d_hh;
    float ax0 = 0.f, ay0 = 0.f, ax1 = 0.f, ay1 = 0.f;
    int i = beg;
    for (; i + 8 <= end; i += 8) {
        int s0 = d_csr[i + 0], s1 = d_csr[i + 1], s2 = d_csr[i + 2], s3 = d_csr[i + 3];
        int s4 = d_csr[i + 4], s5 = d_csr[i + 5], s6 = d_csr[i + 6], s7 = d_csr[i + 7];
        float2 v0 = __half22float2(hp[s0 * 32 + lane]);
        float2 v1 = __half22float2(hp[s1 * 32 + lane]);
        float2 v2 = __half22float2(hp[s2 * 32 + lane]);
        float2 v3 = __half22float2(hp[s3 * 32 + lane]);
        float2 v4 = __half22float2(hp[s4 * 32 + lane]);
        float2 v5 = __half22float2(hp[s5 * 32 + lane]);
        float2 v6 = __half22float2(hp[s6 * 32 + lane]);
        float2 v7 = __half22float2(hp[s7 * 32 + lane]);
        ax0 += v0.x + v1.x + v2.x + v3.x;
        ay0 += v0.y + v1.y + v2.y + v3.y;
        ax1 += v4.x + v5.x + v6.x + v7.x;
        ay1 += v4.y + v5.y + v6.y + v7.y;
    }
    for (; i < end; i++) {
        float2 v = __half22float2(hp[d_csr[i] * 32 + lane]);
        ax0 += v.x; ay0 += v.y;
    }
    float id = d_invdeg[w];
    ((float2*)d_agg)[w * 32 + lane] = make_float2((ax0 + ax1) * id, (ay0 + ay1) * id);
}

// ---------------- layer: h_out = relu(agg@Wl^T + bl + h@Wr^T) + h --------------
// mode 0: h0->h1, mode 1: h1->h0, mode 2 (dummy/profiling): h0->scr
__global__ void __launch_bounds__(256, 2)
k_layer(int mode, int write_hh,
        const float* __restrict__ Wl, const float* __restrict__ bl,
        const float* __restrict__ Wr) {
    const float* h    = (mode == 1) ? d_h1 : d_h0;
    float*       hout = (mode == 0) ? d_h1 : ((mode == 1) ? d_h0 : d_scr);
    __shared__ float S[2 * HD * WPAD + HD];
    float* Wls = S;
    float* Wrs = S + HD * WPAD;
    float* bls = S + 2 * HD * WPAD;
    int t = threadIdx.x;
    for (int i = t; i < HD * HD; i += 256) {
        int j = i >> 6, k = i & 63;
        Wls[k * WPAD + j] = Wl[i];
        Wrs[k * WPAD + j] = Wr[i];
    }
    if (t < HD) bls[t] = bl[t];
    __syncthreads();

    int p    = t & 127;
    int jh   = t >> 7;
    int base = blockIdx.x * 256;
    int n0 = base + 2 * p, n1 = n0 + 1;
    bool v0 = (n0 < NN), v1 = (n1 < NN);

    unsigned long long accA[16], accB[16];
    {
        const unsigned long long* bp2 = (const unsigned long long*)(bls + jh * 32);
#pragma unroll
        for (int q = 0; q < 16; q++) { accA[q] = bp2[q]; accB[q] = bp2[q]; }
    }

    float oA[32], oB[32];
    if (v0) {
        const float4* __restrict__ arA = (const float4*)(d_agg + n0 * HD);
        const float4* __restrict__ hrA = (const float4*)(h + n0 * HD);
        const float4* __restrict__ arB = (const float4*)(d_agg + n1 * HD);
        const float4* __restrict__ hrB = (const float4*)(h + n1 * HD);
#pragma unroll 2
        for (int k4 = 0; k4 < 16; k4++) {
            float4 aA = arA[k4], hA = hrA[k4];
            float4 aB, hB;
            if (v1) { aB = arB[k4]; hB = hrB[k4]; }
            else    { aB = make_float4(0, 0, 0, 0); hB = aB; }
            float aAv[4] = {aA.x, aA.y, aA.z, aA.w};
            float hAv[4] = {hA.x, hA.y, hA.z, hA.w};
            float aBv[4] = {aB.x, aB.y, aB.z, aB.w};
            float hBv[4] = {hB.x, hB.y, hB.z, hB.w};
#pragma unroll
            for (int kk = 0; kk < 4; kk++) {
                int k = k4 * 4 + kk;
                const ulonglong2* __restrict__ wl =
                    (const ulonglong2*)(Wls + k * WPAD + jh * 32);
                const ulonglong2* __restrict__ wr =
                    (const ulonglong2*)(Wrs + k * WPAD + jh * 32);
                unsigned long long aAp = pack2(aAv[kk]);
                unsigned long long hAp = pack2(hAv[kk]);
                unsigned long long aBp = pack2(aBv[kk]);
                unsigned long long hBp = pack2(hBv[kk]);
#pragma unroll
                for (int j4 = 0; j4 < 8; j4++) {
                    ulonglong2 L = wl[j4];
                    ulonglong2 R = wr[j4];
                    ffma2(accA[2 * j4 + 0], aAp, L.x);
                    ffma2(accA[2 * j4 + 1], aAp, L.y);
                    ffma2(accA[2 * j4 + 0], hAp, R.x);
                    ffma2(accA[2 * j4 + 1], hAp, R.y);
                    ffma2(accB[2 * j4 + 0], aBp, L.x);
                    ffma2(accB[2 * j4 + 1], aBp, L.y);
                    ffma2(accB[2 * j4 + 0], hBp, R.x);
                    ffma2(accB[2 * j4 + 1], hBp, R.y);
                }
            }
        }
#pragma unroll
        for (int q = 0; q < 16; q++) {
            unpack2(accA[q], oA[2 * q], oA[2 * q + 1]);
            unpack2(accB[q], oB[2 * q], oB[2 * q + 1]);
        }
        const float4* __restrict__ resA = (const float4*)(h + n0 * HD + jh * 32);
#pragma unroll
        for (int f = 0; f < 8; f++) {
            float4 r = resA[f];
            oA[4 * f + 0] = fmaxf(oA[4 * f + 0], 0.f) + r.x;
            oA[4 * f + 1] = fmaxf(oA[4 * f + 1], 0.f) + r.y;
            oA[4 * f + 2] = fmaxf(oA[4 * f + 2], 0.f) + r.z;
            oA[4 * f + 3] = fmaxf(oA[4 * f + 3], 0.f) + r.w;
        }
        if (v1) {
            const float4* __restrict__ resB = (const float4*)(h + n1 * HD + jh * 32);
#pragma unroll
            for (int f = 0; f < 8; f++) {
                float4 r = resB[f];
                oB[4 * f + 0] = fmaxf(oB[4 * f + 0], 0.f) + r.x;
                oB[4 * f + 1] = fmaxf(oB[4 * f + 1], 0.f) + r.y;
                oB[4 * f + 2] = fmaxf(oB[4 * f + 2], 0.f) + r.z;
                oB[4 * f + 3] = fmaxf(oB[4 * f + 3], 0.f) + r.w;
            }
        }
    }

    // staged, coalesced output: 2 waves of 128 nodes each (stage reuses W smem)
    float* stage = S;
#pragma unroll
    for (int wv = 0; wv < 2; wv++) {
        __syncthreads();
        if ((p >> 6) == wv && v0) {
            int ln = 2 * (p & 63);
            float4* sA = (float4*)(stage + ln * WPAD + jh * 32);
#pragma unroll
            for (int f = 0; f < 8; f++)
                sA[f] = make_float4(oA[4 * f], oA[4 * f + 1], oA[4 * f + 2], oA[4 * f + 3]);
            if (v1) {
                float4* sB = (float4*)(stage + (ln + 1) * WPAD + jh * 32);
#pragma unroll
                for (int f = 0; f < 8; f++)
                    sB[f] = make_float4(oB[4 * f], oB[4 * f + 1], oB[4 * f + 2], oB[4 * f + 3]);
            }
        }
        __syncthreads();
        for (int i2 = t; i2 < 2048; i2 += 256) {
            int node = i2 >> 4, f = i2 & 15;
            int gn = base + wv * 128 + node;
            if (gn < NN) {
                float4 vv = *(const float4*)(stage + node * WPAD + f * 4);
                *(float4*)(hout + gn * 64 + f * 4) = vv;
                if (write_hh) {
                    __half2 l2 = __floats2half2_rn(vv.x, vv.y);
                    __half2 h2 = __floats2half2_rn(vv.z, vv.w);
                    unsigned int ul = *(unsigned int*)&l2;
                    unsigned int uh = *(unsigned int*)&h2;
                    ((uint2*)d_hh)[gn * 16 + f] = make_uint2(ul, uh);
                }
            }
        }
    }
}

// ---------------- global mean pool (coalesced) ----------------------------------
// 256 threads; each warp owns 64 consecutive rows, reads 2 full rows/iter as
// float4 (coalesced); flushes per-graph partial sums via 4 atomics.
__global__ void k_pool(int sel) {
    const float* __restrict__ h = sel ? d_h1 : d_h0;
    int warp = threadIdx.x >> 5, lane = threadIdx.x & 31;
    int rbase = blockIdx.x * 512 + warp * 64;
    if (rbase >= NN) return;
    int rowoff = lane >> 4;        // 0 or 1
    int f4 = lane & 15;            // which float4 of the row
    float a0 = 0.f, a1 = 0.f, a2 = 0.f, a3 = 0.f;
    int cur = -1;
    for (int it = 0; it < 32; it++) {
        int row = rbase + it * 2 + rowoff;
        if (row >= NN) break;
        int b = d_batch32[row];
        if (b != cur) {
            if (cur >= 0) {
                atomicAdd(&d_gsum[cur * HD + f4 * 4 + 0], a0);
                atomicAdd(&d_gsum[cur * HD + f4 * 4 + 1], a1);
                atomicAdd(&d_gsum[cur * HD + f4 * 4 + 2], a2);
                atomicAdd(&d_gsum[cur * HD + f4 * 4 + 3], a3);
            }
            a0 = a1 = a2 = a3 = 0.f;
            cur = b;
        }
        float4 v = *(const float4*)(h + row * HD + f4 * 4);
        a0 += v.x; a1 += v.y; a2 += v.z; a3 += v.w;
    }
    if (cur >= 0) {
        atomicAdd(&d_gsum[cur * HD + f4 * 4 + 0], a0);
        atomicAdd(&d_gsum[cur * HD + f4 * 4 + 1], a1);
        atomicAdd(&d_gsum[cur * HD + f4 * 4 + 2], a2);
        atomicAdd(&d_gsum[cur * HD + f4 * 4 + 3], a3);
    }
}

// ---------------- heads: policy (blocks 0..48) + value (last block) -------------
__global__ void __launch_bounds__(128)
k_policy(const float* __restrict__ Wp, const float* __restrict__ bp,
         const float* __restrict__ Wv, const float* __restrict__ bv,
         float* __restrict__ out) {
    __shared__ float repr[NG * HD];
    int t = threadIdx.x;
    for (int i = t; i < NG * HD; i += 128) {
        int g = i >> 6;
        repr[i] = d_gsum[i] / fmaxf((float)d_gcnt[g], 1.f);
    }
    __syncthreads();

    if (blockIdx.x == gridDim.x - 1) {   // value head
        int g = t;
        if (g >= NG) return;
        float acc = 0.f;
#pragma unroll
        for (int k = 0; k < HD; k++) acc += repr[g * HD + k] * Wv[k];
        out[NG * NA + g] = tanhf(acc + bv[0]);
        return;
    }

    int a = blockIdx.x * 128 + t;
    if (a >= NA) return;
    float acc[NG];
#pragma unroll
    for (int g = 0; g < NG; g++) acc[g] = 0.f;
    const float4* __restrict__ wr = (const float4*)(Wp + a * HD);
#pragma unroll 2
    for (int k4 = 0; k4 < 16; k4++) {
        float4 w = wr[k4];
#pragma unroll
        for (int g = 0; g < NG; g++) {
            float4 r = *(const float4*)(&repr[g * HD + k4 * 4]);
            acc[g] += w.x * r.x + w.y * r.y + w.z * r.z + w.w * r.w;
        }
    }
    float bias = bp[a];
#pragma unroll
    for (int g = 0; g < NG; g++) out[g * NA + a] = acc[g] + bias;
}

// ---------------- launcher -----------------------------------------------------
extern "C" void kernel_launch(void* const* d_in, const int* in_sizes, int n_in,
                              void* d_out, int out_size) {
    const float* x     = (const float*)d_in[0];
    const void*  edge  = d_in[1];
    const void*  batch = d_in[2];
    const float* Wenc  = (const float*)d_in[3];
    const float* benc  = (const float*)d_in[4];
    const float* Wl    = (const float*)d_in[5];
    const float* bl    = (const float*)d_in[6];
    const float* Wr    = (const float*)d_in[7];
    const float* Wp    = (const float*)d_in[8];
    const float* bp    = (const float*)d_in[9];
    const float* Wv    = (const float*)d_in[10];
    const float* bv    = (const float*)d_in[11];
    float* out = (float*)d_out;

    k_encoder<<<(NN * 32 + 255) / 256, 256>>>(x, Wenc, benc);      // idx 0
    k_convert_edges<<<(2 * NE + 255) / 256, 256>>>(edge);          // idx 1
    k_scan_a<<<98, 256>>>();                                       // idx 2

    // INSTRUMENTATION: dummy layer at profiled stream index 3.
    // mode 2: reads h0 (fresh) + d_agg (stale but identical each replay),
    // writes d_scr (never read), write_hh=0. Deterministic; no aliasing.
    k_layer<<<(NN + 255) / 256, 256>>>(2, 0, Wl, bl, Wr);          // idx 3 (profiled)

    k_scan_c<<<(NN + 255) / 256, 256>>>(batch);                    // idx 4
    k_scatter<<<(NE + 255) / 256, 256>>>();                        // idx 5

    for (int i = 0; i < NL; i++) {
        k_aggregate<<<(NN * 32 + 255) / 256, 256>>>();
        k_layer<<<(NN + 255) / 256, 256>>>(i & 1, (i < NL - 1) ? 1 : 0,
                                           Wl + i * HD * HD, bl + i * HD,
                                           Wr + i * HD * HD);
    }

    k_pool<<<(NN + 511) / 512, 256>>>(0);   // final h is d_h0 after 4 layers
    k_policy<<<(NA + 127) / 128 + 1, 128>>>(Wp, bp, Wv, bv, out);
}

// round 10
// speedup vs baseline: 1.1407x; 1.1008x over previous
#include <cuda_runtime.h>
#include <cuda_fp16.h>
#include <math.h>

#define NN 100000
#define NE 3200000
#define FIN 32
#define HD 64
#define NL 4
#define NA 6158
#define NG 64
#define WPAD 68

// ---------------- scratch (device globals; no allocation allowed) -------------
__device__ int   d_flag;
__device__ int   d_src[NE];
__device__ int   d_dst[NE];
__device__ int   d_batch32[NN];
__device__ int   d_deg[NN];
__device__ int   d_rowptr[NN + 1];
__device__ int   d_cursor[NN];
__device__ int   d_csr[NE];
__device__ float d_invdeg[NN];
__device__ float d_h0[NN * HD];
__device__ float d_h1[NN * HD];
__device__ __half2 d_hh[NN * 32];
__device__ float d_agg[NN * HD];
__device__ float d_gsum[NG * HD];
__device__ int   d_gcnt[NG];
__device__ int   d_part[256];

// ---------------- f32x2 packed-FMA helpers -------------------------------------
__device__ __forceinline__ unsigned long long pack2(float x) {
    unsigned long long r;
    asm("mov.b64 %0, {%1, %1};" : "=l"(r) : "f"(x));
    return r;
}
__device__ __forceinline__ void ffma2(unsigned long long& d,
                                      unsigned long long a,
                                      unsigned long long b) {
    asm("fma.rn.f32x2 %0, %1, %2, %0;" : "+l"(d) : "l"(a), "l"(b));
}
__device__ __forceinline__ void unpack2(unsigned long long v, float& lo, float& hi) {
    asm("mov.b64 {%0, %1}, %2;" : "=f"(lo), "=f"(hi) : "l"(v));
}

// ---------------- encoder: h0 = relu(x @ W_enc^T + b_enc) + zero accumulators --
__global__ void k_encoder(const float* __restrict__ x,
                          const float* __restrict__ Wenc,
                          const float* __restrict__ benc) {
    __shared__ float Ws[FIN * HD];
    __shared__ float bs[HD];
    int t = threadIdx.x;
    int gid = blockIdx.x * blockDim.x + t;
    if (gid < NN) d_deg[gid] = 0;
    if (gid < NG) d_gcnt[gid] = 0;
    if (gid < NG * HD) d_gsum[gid] = 0.f;

    for (int i = t; i < HD * FIN; i += blockDim.x) {
        int j = i / FIN, k = i % FIN;
        Ws[k * HD + j] = Wenc[i];
    }
    if (t < HD) bs[t] = benc[t];
    __syncthreads();
    if (gid >= NN * 32) return;
    int n = gid >> 5, j2 = gid & 31;
    int j = 2 * j2;
    const float* xr = x + n * FIN;
    float a0 = bs[j], a1 = bs[j + 1];
#pragma unroll
    for (int k = 0; k < FIN; k += 4) {
        float4 xv = *(const float4*)(xr + k);
        float2 w0 = *(const float2*)(&Ws[k * HD + j]);
        float2 w1 = *(const float2*)(&Ws[(k + 1) * HD + j]);
        float2 w2 = *(const float2*)(&Ws[(k + 2) * HD + j]);
        float2 w3 = *(const float2*)(&Ws[(k + 3) * HD + j]);
        a0 += xv.x * w0.x + xv.y * w1.x + xv.z * w2.x + xv.w * w3.x;
        a1 += xv.x * w0.y + xv.y * w1.y + xv.z * w2.y + xv.w * w3.y;
    }
    a0 = fmaxf(a0, 0.f);
    a1 = fmaxf(a1, 0.f);
    ((float2*)d_h0)[gid] = make_float2(a0, a1);
    d_hh[gid] = __floats2half2_rn(a0, a1);
}

// convert edges + degree count; dtype detection done block-locally (warp ballot)
__global__ void k_convert_edges(const void* edge) {
    __shared__ int sflag;
    if (threadIdx.x < 32) {
        const unsigned int* w = (const unsigned int*)edge;
        unsigned int m0 = __ballot_sync(0xffffffffu, w[2 * threadIdx.x + 1] == 0u);
        unsigned int m1 = __ballot_sync(0xffffffffu, w[2 * (threadIdx.x + 32) + 1] == 0u);
        if (threadIdx.x == 0) {
            int f = (__popc(m0) + __popc(m1) >= 60) ? 1 : 0;
            sflag = f;
            if (blockIdx.x == 0) d_flag = f;   // for k_scan_c (batch conversion)
        }
    }
    __syncthreads();
    int i = blockIdx.x * blockDim.x + threadIdx.x;
    if (i >= 2 * NE) return;
    int v;
    if (sflag) v = (int)((const long long*)edge)[i];
    else       v = ((const int*)edge)[i];
    if (i < NE) d_src[i] = v;
    else        { d_dst[i - NE] = v; atomicAdd(&d_deg[v], 1); }
}

// ---------------- CSR build (scan over degrees) --------------------------------
__global__ void k_scan_a() {
    __shared__ int ts[256];
    int b = blockIdx.x, t = threadIdx.x;
    int base = b * 1024 + t * 4;
    int v[4];
    int s = 0;
#pragma unroll
    for (int j = 0; j < 4; j++) {
        int idx = base + j;
        v[j] = (idx < NN) ? d_deg[idx] : 0;
        s += v[j];
    }
    ts[t] = s;
    __syncthreads();
    for (int off = 1; off < 256; off <<= 1) {
        int x = (t >= off) ? ts[t - off] : 0;
        __syncthreads();
        ts[t] += x;
        __syncthreads();
    }
    int run = ts[t] - s;
#pragma unroll
    for (int j = 0; j < 4; j++) {
        int idx = base + j;
        if (idx < NN) d_rowptr[idx] = run;
        run += v[j];
    }
    if (t == 255) d_part[b] = ts[255];
}

// scan finalize (partial-scan fused, block-redundant) + invdeg + batch + counts
__global__ void k_scan_c(const void* batch) {
    __shared__ int ps[128];
    int t = threadIdx.x;
    int orig = (t < 98) ? d_part[t] : 0;
    if (t < 128) ps[t] = orig;
    __syncthreads();
    for (int off = 1; off < 128; off <<= 1) {
        int x = (t >= off && t < 128) ? ps[t - off] : 0;
        __syncthreads();
        if (t < 128) ps[t] += x;
        __syncthreads();
    }
    if (t < 128) ps[t] -= orig;   // exclusive
    __syncthreads();

    int i = blockIdx.x * blockDim.x + t;
    if (i == 0) d_rowptr[NN] = NE;
    if (i >= NN) return;
    int r = d_rowptr[i] + ps[i >> 10];
    d_rowptr[i] = r;
    d_cursor[i] = r;
    d_invdeg[i] = 1.0f / fmaxf((float)d_deg[i], 1.0f);
    int b;
    if (d_flag) b = (int)((const long long*)batch)[i];
    else        b = ((const int*)batch)[i];
    d_batch32[i] = b;
    atomicAdd(&d_gcnt[b], 1);
}

__global__ void k_scatter() {
    int e = blockIdx.x * blockDim.x + threadIdx.x;
    if (e >= NE) return;
    int dd = d_dst[e];
    int pos = atomicAdd(&d_cursor[dd], 1);
    d_csr[pos] = d_src[e];
}

// ---------------- aggregation: agg[n] = mean_{e: dst=n} h_fp16[src[e]] ---------
__global__ void k_aggregate() {
    int w = (blockIdx.x * blockDim.x + threadIdx.x) >> 5;
    if (w >= NN) return;
    int lane = threadIdx.x & 31;
    int beg = d_rowptr[w], end = d_rowptr[w + 1];
    const __half2* __restrict__ hp = d_hh;
    float ax0 = 0.f, ay0 = 0.f, ax1 = 0.f, ay1 = 0.f;
    int i = beg;
    for (; i + 8 <= end; i += 8) {
        int s0 = d_csr[i + 0], s1 = d_csr[i + 1], s2 = d_csr[i + 2], s3 = d_csr[i + 3];
        int s4 = d_csr[i + 4], s5 = d_csr[i + 5], s6 = d_csr[i + 6], s7 = d_csr[i + 7];
        float2 v0 = __half22float2(hp[s0 * 32 + lane]);
        float2 v1 = __half22float2(hp[s1 * 32 + lane]);
        float2 v2 = __half22float2(hp[s2 * 32 + lane]);
        float2 v3 = __half22float2(hp[s3 * 32 + lane]);
        float2 v4 = __half22float2(hp[s4 * 32 + lane]);
        float2 v5 = __half22float2(hp[s5 * 32 + lane]);
        float2 v6 = __half22float2(hp[s6 * 32 + lane]);
        float2 v7 = __half22float2(hp[s7 * 32 + lane]);
        ax0 += v0.x + v1.x + v2.x + v3.x;
        ay0 += v0.y + v1.y + v2.y + v3.y;
        ax1 += v4.x + v5.x + v6.x + v7.x;
        ay1 += v4.y + v5.y + v6.y + v7.y;
    }
    for (; i < end; i++) {
        float2 v = __half22float2(hp[d_csr[i] * 32 + lane]);
        ax0 += v.x; ay0 += v.y;
    }
    float id = d_invdeg[w];
    ((float2*)d_agg)[w * 32 + lane] = make_float2((ax0 + ax1) * id, (ay0 + ay1) * id);
}

// ---------------- layer v3: wave-aligned nodes + split epilogue (no spills) -----
// thread handles nodes (base+p, base+128+p); epilogue per wave so accA/oA die
// before accB/oB peak. Peak regs ~96 -> fits 128-reg cap, no local spills.
__global__ void __launch_bounds__(256, 2)
k_layer(int mode, int write_hh,
        const float* __restrict__ Wl, const float* __restrict__ bl,
        const float* __restrict__ Wr) {
    const float* h    = (mode == 1) ? d_h1 : d_h0;
    float*       hout = (mode == 0) ? d_h1 : d_h0;
    __shared__ float S[2 * HD * WPAD + HD];
    float* Wls = S;
    float* Wrs = S + HD * WPAD;
    float* bls = S + 2 * HD * WPAD;
    int t = threadIdx.x;
    for (int i = t; i < HD * HD; i += 256) {
        int j = i >> 6, k = i & 63;
        Wls[k * WPAD + j] = Wl[i];
        Wrs[k * WPAD + j] = Wr[i];
    }
    if (t < HD) bls[t] = bl[t];
    __syncthreads();

    int p    = t & 127;
    int jh   = t >> 7;
    int base = blockIdx.x * 256;
    int n0 = base + p;         // wave-0 node: ALWAYS < NN (100000 mod 256 = 160 >= 128)
    int n1 = base + 128 + p;   // wave-1 node: needs guard in last block
    bool v1 = (n1 < NN);

    unsigned long long accA[16], accB[16];
    {
        const unsigned long long* bp2 = (const unsigned long long*)(bls + jh * 32);
#pragma unroll
        for (int q = 0; q < 16; q++) { accA[q] = bp2[q]; accB[q] = bp2[q]; }
    }

    {
        const float4* __restrict__ arA = (const float4*)(d_agg + n0 * HD);
        const float4* __restrict__ hrA = (const float4*)(h + n0 * HD);
        const float4* __restrict__ arB = (const float4*)(d_agg + n1 * HD);
        const float4* __restrict__ hrB = (const float4*)(h + n1 * HD);
#pragma unroll 2
        for (int k4 = 0; k4 < 16; k4++) {
            float4 aA = arA[k4], hA = hrA[k4];
            float4 aB, hB;
            if (v1) { aB = arB[k4]; hB = hrB[k4]; }
            else    { aB = make_float4(0, 0, 0, 0); hB = aB; }
            float aAv[4] = {aA.x, aA.y, aA.z, aA.w};
            float hAv[4] = {hA.x, hA.y, hA.z, hA.w};
            float aBv[4] = {aB.x, aB.y, aB.z, aB.w};
            float hBv[4] = {hB.x, hB.y, hB.z, hB.w};
#pragma unroll
            for (int kk = 0; kk < 4; kk++) {
                int k = k4 * 4 + kk;
                const ulonglong2* __restrict__ wl =
                    (const ulonglong2*)(Wls + k * WPAD + jh * 32);
                const ulonglong2* __restrict__ wr =
                    (const ulonglong2*)(Wrs + k * WPAD + jh * 32);
                unsigned long long aAp = pack2(aAv[kk]);
                unsigned long long hAp = pack2(hAv[kk]);
                unsigned long long aBp = pack2(aBv[kk]);
                unsigned long long hBp = pack2(hBv[kk]);
#pragma unroll
                for (int j4 = 0; j4 < 8; j4++) {
                    ulonglong2 L = wl[j4];
                    ulonglong2 R = wr[j4];
                    ffma2(accA[2 * j4 + 0], aAp, L.x);
                    ffma2(accA[2 * j4 + 1], aAp, L.y);
                    ffma2(accA[2 * j4 + 0], hAp, R.x);
                    ffma2(accA[2 * j4 + 1], hAp, R.y);
                    ffma2(accB[2 * j4 + 0], aBp, L.x);
                    ffma2(accB[2 * j4 + 1], aBp, L.y);
                    ffma2(accB[2 * j4 + 0], hBp, R.x);
                    ffma2(accB[2 * j4 + 1], hBp, R.y);
                }
            }
        }
    }

    float* stage = S;   // reuse W smem (all W reads complete)
    float o[32];

    // ---------------- wave 0 (nodes base .. base+127, always valid) -----------
#pragma unroll
    for (int q = 0; q < 16; q++) unpack2(accA[q], o[2 * q], o[2 * q + 1]);
    {
        const float4* __restrict__ res = (const float4*)(h + n0 * HD + jh * 32);
#pragma unroll
        for (int f = 0; f < 8; f++) {
            float4 r = res[f];
            o[4 * f + 0] = fmaxf(o[4 * f + 0], 0.f) + r.x;
            o[4 * f + 1] = fmaxf(o[4 * f + 1], 0.f) + r.y;
            o[4 * f + 2] = fmaxf(o[4 * f + 2], 0.f) + r.z;
            o[4 * f + 3] = fmaxf(o[4 * f + 3], 0.f) + r.w;
        }
    }
    __syncthreads();   // main-loop W reads done (all threads)
    {
        float4* s4 = (float4*)(stage + p * WPAD + jh * 32);
#pragma unroll
        for (int f = 0; f < 8; f++)
            s4[f] = make_float4(o[4 * f], o[4 * f + 1], o[4 * f + 2], o[4 * f + 3]);
    }
    __syncthreads();
    for (int i2 = t; i2 < 2048; i2 += 256) {
        int node = i2 >> 4, f = i2 & 15;
        int gn = base + node;   // wave-0 nodes always valid
        float4 vv = *(const float4*)(stage + node * WPAD + f * 4);
        *(float4*)(hout + gn * 64 + f * 4) = vv;
        if (write_hh) {
            __half2 l2 = __floats2half2_rn(vv.x, vv.y);
            __half2 h2 = __floats2half2_rn(vv.z, vv.w);
            unsigned int ul = *(unsigned int*)&l2;
            unsigned int uh = *(unsigned int*)&h2;
            ((uint2*)d_hh)[gn * 16 + f] = make_uint2(ul, uh);
        }
    }

    // ---------------- wave 1 (nodes base+128 .. base+255, guarded) ------------
#pragma unroll
    for (int q = 0; q < 16; q++) unpack2(accB[q], o[2 * q], o[2 * q + 1]);
    if (v1) {
        const float4* __restrict__ res = (const float4*)(h + n1 * HD + jh * 32);
#pragma unroll
        for (int f = 0; f < 8; f++) {
            float4 r = res[f];
            o[4 * f + 0] = fmaxf(o[4 * f + 0], 0.f) + r.x;
            o[4 * f + 1] = fmaxf(o[4 * f + 1], 0.f) + r.y;
            o[4 * f + 2] = fmaxf(o[4 * f + 2], 0.f) + r.z;
            o[4 * f + 3] = fmaxf(o[4 * f + 3], 0.f) + r.w;
        }
    }
    __syncthreads();   // wave-0 stage reads done
    if (v1) {
        float4* s4 = (float4*)(stage + p * WPAD + jh * 32);
#pragma unroll
        for (int f = 0; f < 8; f++)
            s4[f] = make_float4(o[4 * f], o[4 * f + 1], o[4 * f + 2], o[4 * f + 3]);
    }
    __syncthreads();
    for (int i2 = t; i2 < 2048; i2 += 256) {
        int node = i2 >> 4, f = i2 & 15;
        int gn = base + 128 + node;
        if (gn < NN) {
            float4 vv = *(const float4*)(stage + node * WPAD + f * 4);
            *(float4*)(hout + gn * 64 + f * 4) = vv;
            if (write_hh) {
                __half2 l2 = __floats2half2_rn(vv.x, vv.y);
                __half2 h2 = __floats2half2_rn(vv.z, vv.w);
                unsigned int ul = *(unsigned int*)&l2;
                unsigned int uh = *(unsigned int*)&h2;
                ((uint2*)d_hh)[gn * 16 + f] = make_uint2(ul, uh);
            }
        }
    }
}

// ---------------- global mean pool (coalesced) ----------------------------------
__global__ void k_pool(int sel) {
    const float* __restrict__ h = sel ? d_h1 : d_h0;
    int warp = threadIdx.x >> 5, lane = threadIdx.x & 31;
    int rbase = blockIdx.x * 512 + warp * 64;
    if (rbase >= NN) return;
    int rowoff = lane >> 4;
    int f4 = lane & 15;
    float a0 = 0.f, a1 = 0.f, a2 = 0.f, a3 = 0.f;
    int cur = -1;
    for (int it = 0; it < 32; it++) {
        int row = rbase + it * 2 + rowoff;
        if (row >= NN) break;
        int b = d_batch32[row];
        if (b != cur) {
            if (cur >= 0) {
                atomicAdd(&d_gsum[cur * HD + f4 * 4 + 0], a0);
                atomicAdd(&d_gsum[cur * HD + f4 * 4 + 1], a1);
                atomicAdd(&d_gsum[cur * HD + f4 * 4 + 2], a2);
                atomicAdd(&d_gsum[cur * HD + f4 * 4 + 3], a3);
            }
            a0 = a1 = a2 = a3 = 0.f;
            cur = b;
        }
        float4 v = *(const float4*)(h + row * HD + f4 * 4);
        a0 += v.x; a1 += v.y; a2 += v.z; a3 += v.w;
    }
    if (cur >= 0) {
        atomicAdd(&d_gsum[cur * HD + f4 * 4 + 0], a0);
        atomicAdd(&d_gsum[cur * HD + f4 * 4 + 1], a1);
        atomicAdd(&d_gsum[cur * HD + f4 * 4 + 2], a2);
        atomicAdd(&d_gsum[cur * HD + f4 * 4 + 3], a3);
    }
}

// ---------------- heads: policy (blocks 0..48) + value (last block) -------------
__global__ void __launch_bounds__(128)
k_policy(const float* __restrict__ Wp, const float* __restrict__ bp,
         const float* __restrict__ Wv, const float* __restrict__ bv,
         float* __restrict__ out) {
    __shared__ float repr[NG * HD];
    int t = threadIdx.x;
    for (int i = t; i < NG * HD; i += 128) {
        int g = i >> 6;
        repr[i] = d_gsum[i] / fmaxf((float)d_gcnt[g], 1.f);
    }
    __syncthreads();

    if (blockIdx.x == gridDim.x - 1) {   // value head
        int g = t;
        if (g >= NG) return;
        float acc = 0.f;
#pragma unroll
        for (int k = 0; k < HD; k++) acc += repr[g * HD + k] * Wv[k];
        out[NG * NA + g] = tanhf(acc + bv[0]);
        return;
    }

    int a = blockIdx.x * 128 + t;
    if (a >= NA) return;
    float acc[NG];
#pragma unroll
    for (int g = 0; g < NG; g++) acc[g] = 0.f;
    const float4* __restrict__ wr = (const float4*)(Wp + a * HD);
#pragma unroll 2
    for (int k4 = 0; k4 < 16; k4++) {
        float4 w = wr[k4];
#pragma unroll
        for (int g = 0; g < NG; g++) {
            float4 r = *(const float4*)(&repr[g * HD + k4 * 4]);
            acc[g] += w.x * r.x + w.y * r.y + w.z * r.z + w.w * r.w;
        }
    }
    float bias = bp[a];
#pragma unroll
    for (int g = 0; g < NG; g++) out[g * NA + a] = acc[g] + bias;
}

// ---------------- launcher -----------------------------------------------------
extern "C" void kernel_launch(void* const* d_in, const int* in_sizes, int n_in,
                              void* d_out, int out_size) {
    const float* x     = (const float*)d_in[0];
    const void*  edge  = d_in[1];
    const void*  batch = d_in[2];
    const float* Wenc  = (const float*)d_in[3];
    const float* benc  = (const float*)d_in[4];
    const float* Wl    = (const float*)d_in[5];
    const float* bl    = (const float*)d_in[6];
    const float* Wr    = (const float*)d_in[7];
    const float* Wp    = (const float*)d_in[8];
    const float* bp    = (const float*)d_in[9];
    const float* Wv    = (const float*)d_in[10];
    const float* bv    = (const float*)d_in[11];
    float* out = (float*)d_out;

    k_encoder<<<(NN * 32 + 255) / 256, 256>>>(x, Wenc, benc);
    k_convert_edges<<<(2 * NE + 255) / 256, 256>>>(edge);
    k_scan_a<<<98, 256>>>();
    k_scan_c<<<(NN + 255) / 256, 256>>>(batch);
    k_scatter<<<(NE + 255) / 256, 256>>>();

    for (int i = 0; i < NL; i++) {
        k_aggregate<<<(NN * 32 + 255) / 256, 256>>>();
        k_layer<<<(NN + 255) / 256, 256>>>(i & 1, (i < NL - 1) ? 1 : 0,
                                           Wl + i * HD * HD, bl + i * HD,
                                           Wr + i * HD * HD);
    }

    k_pool<<<(NN + 511) / 512, 256>>>(0);   // final h is d_h0 after 4 layers
    k_policy<<<(NA + 127) / 128 + 1, 128>>>(Wp, bp, Wv, bv, out);
}